// round 2
// baseline (speedup 1.0000x reference)
#include <cuda_runtime.h>

#define BATCH 1024
#define TLEN  512
#define KDIM  64
#define LOG2E 1.4426950408889634f
#define LN2   0.6931471805599453f

__device__ float g_partials[BATCH];

__device__ __forceinline__ float ex2(float x) {
    float y; asm("ex2.approx.ftz.f32 %0, %1;" : "=f"(y) : "f"(x)); return y;
}
__device__ __forceinline__ float lg2(float x) {
    float y; asm("lg2.approx.f32 %0, %1;" : "=f"(y) : "f"(x)); return y;
}

__global__ __launch_bounds__(KDIM) void crf_fwd_kernel(
    const float* __restrict__ logits,   // [B, T, K]
    const float* __restrict__ trans,    // [K, K]
    const int*   __restrict__ gold,     // [B, T]
    const int*   __restrict__ seq_len)  // [B]
{
    const int b = blockIdx.x;
    const int j = threadIdx.x;
    const int w = j >> 5;               // warp id (0 or 1)
    const int L = seq_len[b];

    __shared__ float4 p_sh[KDIM / 4];   // exp-shifted alpha, read as float4
    __shared__ float  wred[2];          // per-warp maxes
    __shared__ float  acc_sh[2];        // unary+pair partials per warp

    // E row in registers: e[i] = exp(trans[j,i]) = 2^(trans[j,i]*log2e)
    float e[KDIM];
    #pragma unroll
    for (int i = 0; i < KDIM; i++)
        e[i] = ex2(trans[j * KDIM + i] * LOG2E);

    const float* lb = logits + (size_t)b * TLEN * KDIM;
    const int*   gb = gold + b * TLEN;

    // unary (t < L) + pairwise (t < L-1) partial sums, strided over threads
    float us = 0.f;
    for (int t = j; t < L; t += KDIM) {
        int g = gb[t];
        us += lb[t * KDIM + g];
        if (t < L - 1)
            us += trans[g * KDIM + gb[t + 1]];
    }
    #pragma unroll
    for (int off = 16; off; off >>= 1)
        us += __shfl_xor_sync(0xffffffffu, us, off);
    if ((j & 31) == 0) acc_sh[w] = us;
    // (covered by the first in-loop __syncthreads before acc_sh is read)

    // alpha in log2 domain
    float a2 = lb[j] * LOG2E;

    // prefetch logits for t=1
    float lt = lb[KDIM + j];

    for (int t = 1; t < L; t++) {
        // prefetch next step's logit while this step computes
        int tn = (t + 1 < L) ? (t + 1) : t;
        float lt_nx = lb[tn * KDIM + j];

        // warp-local max (5 shfl) — no cross-warp barrier needed before ex2
        float m = a2;
        #pragma unroll
        for (int off = 16; off; off >>= 1)
            m = fmaxf(m, __shfl_xor_sync(0xffffffffu, m, off));

        ((float*)p_sh)[j] = ex2(a2 - m);   // shifted by OWN warp max
        if ((j & 31) == 0) wred[w] = m;
        __syncthreads();

        float m0 = wred[0], m1 = wred[1];
        float M2 = fmaxf(m0, m1);

        // two partial matvec sums, one per warp-half of p, vector loads
        float s0 = 0.f, s1 = 0.f;
        #pragma unroll
        for (int q = 0; q < 8; q++) {
            float4 p = p_sh[q];
            s0 = fmaf(e[4*q + 0], p.x, s0);
            s0 = fmaf(e[4*q + 1], p.y, s0);
            s0 = fmaf(e[4*q + 2], p.z, s0);
            s0 = fmaf(e[4*q + 3], p.w, s0);
        }
        #pragma unroll
        for (int q = 8; q < 16; q++) {
            float4 p = p_sh[q];
            s1 = fmaf(e[4*q + 0], p.x, s1);
            s1 = fmaf(e[4*q + 1], p.y, s1);
            s1 = fmaf(e[4*q + 2], p.z, s1);
            s1 = fmaf(e[4*q + 3], p.w, s1);
        }

        // rescale each warp-half by 2^(m_w - M) and combine
        float s = fmaf(ex2(m0 - M2), s0, ex2(m1 - M2) * s1);

        a2 = lg2(s) + M2 + lt * LOG2E;
        lt = lt_nx;
        __syncthreads();   // protect p_sh/wred reuse next iteration
    }

    // third = logsumexp_e(alpha_final), same warp-local-max trick
    {
        float m = a2;
        #pragma unroll
        for (int off = 16; off; off >>= 1)
            m = fmaxf(m, __shfl_xor_sync(0xffffffffu, m, off));
        ((float*)p_sh)[j] = ex2(a2 - m);
        if ((j & 31) == 0) wred[w] = m;
        __syncthreads();

        if (j == 0) {
            float m0 = wred[0], m1 = wred[1];
            float M2 = fmaxf(m0, m1);
            const float* pp = (const float*)p_sh;
            float s0 = 0.f, s1 = 0.f;
            #pragma unroll
            for (int i = 0; i < 32; i++) { s0 += pp[i]; s1 += pp[32 + i]; }
            float s = ex2(m0 - M2) * s0 + ex2(m1 - M2) * s1;
            float third = (M2 + lg2(s)) * LN2;
            g_partials[b] = acc_sh[0] + acc_sh[1] - third;
        }
    }
}

__global__ __launch_bounds__(256) void crf_reduce_kernel(float* __restrict__ out)
{
    __shared__ float sh[256];
    int t = threadIdx.x;
    float s = 0.f;
    for (int i = t; i < BATCH; i += 256)
        s += g_partials[i];
    sh[t] = s;
    __syncthreads();
    #pragma unroll
    for (int off = 128; off; off >>= 1) {
        if (t < off) sh[t] += sh[t + off];
        __syncthreads();
    }
    if (t == 0)
        out[0] = -sh[0] / (float)BATCH;
}

extern "C" void kernel_launch(void* const* d_in, const int* in_sizes, int n_in,
                              void* d_out, int out_size)
{
    const float* logits  = (const float*)d_in[0];
    const float* trans   = (const float*)d_in[1];
    const int*   gold    = (const int*)d_in[2];
    const int*   seq_len = (const int*)d_in[3];
    float* out = (float*)d_out;

    crf_fwd_kernel<<<BATCH, KDIM>>>(logits, trans, gold, seq_len);
    crf_reduce_kernel<<<1, 256>>>(out);
}

// round 4
// speedup vs baseline: 1.2562x; 1.2562x over previous
#include <cuda_runtime.h>

#define BATCH 1024
#define TLEN  512
#define KDIM  64
#define LOG2E 1.4426950408889634f
#define LN2   0.6931471805599453f

__device__ float g_partials[BATCH];

__device__ __forceinline__ float ex2(float x) {
    float y; asm("ex2.approx.ftz.f32 %0, %1;" : "=f"(y) : "f"(x)); return y;
}
__device__ __forceinline__ float lg2(float x) {
    float y; asm("lg2.approx.f32 %0, %1;" : "=f"(y) : "f"(x)); return y;
}
__device__ __forceinline__ unsigned long long ffma2(
    unsigned long long a, unsigned long long b, unsigned long long c) {
    unsigned long long d;
    asm("fma.rn.f32x2 %0, %1, %2, %3;" : "=l"(d) : "l"(a), "l"(b), "l"(c));
    return d;
}
__device__ __forceinline__ unsigned long long pack2(float lo, float hi) {
    unsigned long long u;
    asm("mov.b64 %0, {%1, %2};" : "=l"(u) : "f"(lo), "f"(hi));
    return u;
}
__device__ __forceinline__ void unpack2(unsigned long long v, float& lo, float& hi) {
    asm("mov.b64 {%0, %1}, %2;" : "=f"(lo), "=f"(hi) : "l"(v));
}

__global__ __launch_bounds__(KDIM) void crf_fwd_kernel(
    const float* __restrict__ logits,   // [B, T, K]
    const float* __restrict__ trans,    // [K, K]
    const int*   __restrict__ gold,     // [B, T]
    const int*   __restrict__ seq_len)  // [B]
{
    const int b = blockIdx.x;
    const int j = threadIdx.x;
    const int w = j >> 5;
    const int L = seq_len[b];

    __shared__ __align__(16) float p_sh[2][KDIM];  // double-buffered exp(alpha - C)
    __shared__ float c_sh[2];                      // lag-2 normalizer (thread 0's alpha)
    __shared__ float wred[2];
    __shared__ float acc_sh[2];

    // E row, packed pairs: ep[i] = ( exp(trans[j,2i]), exp(trans[j,2i+1]) )
    unsigned long long ep[KDIM / 2];
    #pragma unroll
    for (int i = 0; i < KDIM / 2; i++) {
        float lo = ex2(trans[j * KDIM + 2 * i] * LOG2E);
        float hi = ex2(trans[j * KDIM + 2 * i + 1] * LOG2E);
        ep[i] = pack2(lo, hi);
    }

    const float* lb = logits + (size_t)b * TLEN * KDIM;
    const int*   gb = gold + b * TLEN;

    // unary (t < L) + pairwise (t < L-1) partial sums, strided over threads
    float us = 0.f;
    for (int t = j; t < L; t += KDIM) {
        int g = gb[t];
        us += lb[t * KDIM + g];
        if (t < L - 1)
            us += trans[g * KDIM + gb[t + 1]];
    }
    #pragma unroll
    for (int off = 16; off; off >>= 1)
        us += __shfl_xor_sync(0xffffffffu, us, off);
    if ((j & 31) == 0) acc_sh[w] = us;

    if (j == 0) { c_sh[0] = 0.f; c_sh[1] = 0.f; }

    // alpha in log2 domain
    float a2 = lb[j] * LOG2E;
    float lt = lb[KDIM + j];   // prefetch t=1

    __syncthreads();           // c_sh init + acc_sh visible

    for (int t = 1; t < L; t++) {
        const int pb = t & 1;

        // prefetch next step's logit
        int tn = (t + 1 < L) ? (t + 1) : t;
        float lt_nx = lb[tn * KDIM + j];

        // uniform normalizer: thread 0's alpha from 2 steps ago (barrier-ordered)
        float C = c_sh[pb];
        p_sh[pb][j] = ex2(a2 - C);
        __syncthreads();

        // packed-f32x2 matvec: s_j = sum_i E[j,i] * p[i]
        const ulonglong2* pp = (const ulonglong2*)p_sh[pb];
        unsigned long long a0 = 0ull, a1 = 0ull, a2p = 0ull, a3 = 0ull;
        #pragma unroll
        for (int q = 0; q < 8; q += 2) {
            ulonglong2 v0 = pp[q];
            ulonglong2 v1 = pp[q + 1];
            a0 = ffma2(ep[2 * q + 0], v0.x, a0);
            a1 = ffma2(ep[2 * q + 1], v0.y, a1);
            a2p = ffma2(ep[2 * q + 2], v1.x, a2p);
            a3 = ffma2(ep[2 * q + 3], v1.y, a3);
        }
        #pragma unroll
        for (int q = 8; q < 16; q += 2) {
            ulonglong2 v0 = pp[q];
            ulonglong2 v1 = pp[q + 1];
            a0 = ffma2(ep[2 * q + 0], v0.x, a0);
            a1 = ffma2(ep[2 * q + 1], v0.y, a1);
            a2p = ffma2(ep[2 * q + 2], v1.x, a2p);
            a3 = ffma2(ep[2 * q + 3], v1.y, a3);
        }
        float l0, h0, l1, h1, l2, h2, l3, h3;
        unpack2(a0, l0, h0); unpack2(a1, l1, h1);
        unpack2(a2p, l2, h2); unpack2(a3, l3, h3);
        float s = ((l0 + h0) + (l1 + h1)) + ((l2 + h2) + (l3 + h3));

        a2 = lg2(s) + C + lt * LOG2E;
        lt = lt_nx;
        if (j == 0) c_sh[pb] = a2;   // becomes C at step t+2
    }

    // third = logsumexp_e(alpha_final) — one-shot, warp-max version
    __syncthreads();   // retire last matvec reads before reusing p_sh[0]
    {
        float m = a2;
        #pragma unroll
        for (int off = 16; off; off >>= 1)
            m = fmaxf(m, __shfl_xor_sync(0xffffffffu, m, off));
        p_sh[0][j] = ex2(a2 - m);
        if ((j & 31) == 0) wred[w] = m;
        __syncthreads();

        if (j == 0) {
            float m0 = wred[0], m1 = wred[1];
            float M2 = fmaxf(m0, m1);
            float s0 = 0.f, s1 = 0.f;
            #pragma unroll
            for (int i = 0; i < 32; i++) { s0 += p_sh[0][i]; s1 += p_sh[0][32 + i]; }
            float s = ex2(m0 - M2) * s0 + ex2(m1 - M2) * s1;
            float third = (M2 + lg2(s)) * LN2;
            g_partials[b] = acc_sh[0] + acc_sh[1] - third;
        }
    }
}

__global__ __launch_bounds__(256) void crf_reduce_kernel(float* __restrict__ out)
{
    __shared__ float sh[256];
    int t = threadIdx.x;
    float s = 0.f;
    for (int i = t; i < BATCH; i += 256)
        s += g_partials[i];
    sh[t] = s;
    __syncthreads();
    #pragma unroll
    for (int off = 128; off; off >>= 1) {
        if (t < off) sh[t] += sh[t + off];
        __syncthreads();
    }
    if (t == 0)
        out[0] = -sh[0] / (float)BATCH;
}

extern "C" void kernel_launch(void* const* d_in, const int* in_sizes, int n_in,
                              void* d_out, int out_size)
{
    const float* logits  = (const float*)d_in[0];
    const float* trans   = (const float*)d_in[1];
    const int*   gold    = (const int*)d_in[2];
    const int*   seq_len = (const int*)d_in[3];
    float* out = (float*)d_out;

    crf_fwd_kernel<<<BATCH, KDIM>>>(logits, trans, gold, seq_len);
    crf_reduce_kernel<<<1, 256>>>(out);
}

// round 5
// speedup vs baseline: 1.6026x; 1.2758x over previous
#include <cuda_runtime.h>

#define BATCH 1024
#define TLEN  512
#define KDIM  64
#define NBLK  148
#define NTHREADS 128
#define WARPS_TOTAL (NBLK * 4)              // 592
#define SECOND_MIN (2 * WARPS_TOTAL - BATCH) // 160
#define LOG2E 1.4426950408889634f
#define LN2   0.6931471805599453f
#define RENORM_MASK 7

__device__ float g_partials[BATCH];
__device__ int   g_order[BATCH];
__device__ float g_E[KDIM * KDIM];
__device__ int   g_done;

typedef unsigned long long u64;

__device__ __forceinline__ float ex2(float x) {
    float y; asm("ex2.approx.ftz.f32 %0, %1;" : "=f"(y) : "f"(x)); return y;
}
__device__ __forceinline__ float lg2(float x) {
    float y; asm("lg2.approx.f32 %0, %1;" : "=f"(y) : "f"(x)); return y;
}
__device__ __forceinline__ u64 ffma2(u64 a, u64 b, u64 c) {
    u64 d; asm("fma.rn.f32x2 %0, %1, %2, %3;" : "=l"(d) : "l"(a), "l"(b), "l"(c)); return d;
}
__device__ __forceinline__ u64 add2(u64 a, u64 b) {
    u64 d; asm("add.rn.f32x2 %0, %1, %2;" : "=l"(d) : "l"(a), "l"(b)); return d;
}
__device__ __forceinline__ u64 mul2(u64 a, u64 b) {
    u64 d; asm("mul.rn.f32x2 %0, %1, %2;" : "=l"(d) : "l"(a), "l"(b)); return d;
}
__device__ __forceinline__ u64 pack2(float lo, float hi) {
    u64 u; asm("mov.b64 %0, {%1, %2};" : "=l"(u) : "f"(lo), "f"(hi)); return u;
}
__device__ __forceinline__ void unpack2(u64 v, float& lo, float& hi) {
    asm("mov.b64 {%0, %1}, %2;" : "=f"(lo), "=f"(hi) : "l"(v));
}

// ---------------------------------------------------------------------------
// Pre-kernel: counting-sort batch indices by seq_len (descending) + build E
// ---------------------------------------------------------------------------
__global__ __launch_bounds__(512) void order_kernel(
    const int* __restrict__ seq_len, const float* __restrict__ trans)
{
    __shared__ int hist[512];
    __shared__ int scan[512];
    __shared__ int cnt[512];
    const int tid = threadIdx.x;

    // E = exp(trans), shared by all warps later
    for (int i = tid; i < KDIM * KDIM; i += 512)
        g_E[i] = ex2(trans[i] * LOG2E);

    hist[tid] = 0; cnt[tid] = 0;
    __syncthreads();
    for (int i = tid; i < BATCH; i += 512)
        atomicAdd(&hist[TLEN - seq_len[i]], 1);   // key = 512 - L in [0, 510]
    __syncthreads();

    // inclusive Hillis-Steele scan
    scan[tid] = hist[tid];
    __syncthreads();
    for (int off = 1; off < 512; off <<= 1) {
        int add = (tid >= off) ? scan[tid - off] : 0;
        __syncthreads();
        scan[tid] += add;
        __syncthreads();
    }

    for (int i = tid; i < BATCH; i += 512) {
        int key = TLEN - seq_len[i];
        int pos = scan[key] - hist[key] + atomicAdd(&cnt[key], 1);
        g_order[pos] = i;
    }
}

// ---------------------------------------------------------------------------
// Main: 1 warp = 1 sequence; linear-domain forward with exact pow2 renorm
// ---------------------------------------------------------------------------
__global__ __launch_bounds__(NTHREADS) void crf_fwd_kernel(
    const float* __restrict__ logits,   // [B, T, K]
    const float* __restrict__ trans,    // [K, K]
    const int*   __restrict__ gold,     // [B, T]
    const int*   __restrict__ seq_len,  // [B]
    float*       __restrict__ out)
{
    __shared__ __align__(16) float p_sh[4][2][KDIM];
    __shared__ float red[NTHREADS];
    __shared__ int   is_last;

    const int lane = threadIdx.x & 31;
    const int wid  = threadIdx.x >> 5;
    const int slot = blockIdx.x * 4 + wid;
    const int j0   = 2 * lane;

    // E rows for my two states (2k, 2k+1), packed pairs along i
    u64 ep0[KDIM / 2], ep1[KDIM / 2];
    #pragma unroll
    for (int m = 0; m < KDIM / 2; m++) {
        ep0[m] = *(const u64*)(g_E + (size_t)j0 * KDIM + 2 * m);
        ep1[m] = *(const u64*)(g_E + (size_t)(j0 + 1) * KDIM + 2 * m);
    }

    #pragma unroll 1
    for (int which = 0; which < 2; which++) {
        int rank;
        if (which == 0)      rank = slot;
        else if (slot >= SECOND_MIN) rank = 2 * WARPS_TOTAL - 1 - slot;
        else break;

        const int b = g_order[rank];
        const int L = seq_len[b];
        const float* lb = logits + (size_t)b * TLEN * KDIM;
        const int*   gb = gold + b * TLEN;

        // unary + pairwise partial sums, strided over lanes
        float us = 0.f;
        for (int t = lane; t < L; t += 32) {
            int g = gb[t];
            us += lb[t * KDIM + g];
            if (t < L - 1)
                us += trans[g * KDIM + gb[t + 1]];
        }

        // p = exp(alpha0), packed for states (2k, 2k+1)
        u64 p = pack2(ex2(lb[j0] * LOG2E), ex2(lb[j0 + 1] * LOG2E));
        int C2 = 0;

        // distance-2 logit prefetch
        float2 ltA = *(const float2*)(lb + KDIM + j0);
        float2 ltB = (L > 2) ? *(const float2*)(lb + 2 * KDIM + j0) : ltA;

        float* const buf0 = p_sh[wid][0];
        float* const buf1 = p_sh[wid][1];

        for (int t = 1; t < L; t++) {
            // U = exp(logit_t) * 2^-6, computed off the critical chain
            u64 U = pack2(ex2(fmaf(ltA.x, LOG2E, -6.f)),
                          ex2(fmaf(ltA.y, LOG2E, -6.f)));
            ltA = ltB;
            if (t + 2 < L) ltB = *(const float2*)(lb + (t + 2) * KDIM + j0);

            float* buf = (t & 1) ? buf1 : buf0;
            *(u64*)(buf + j0) = p;
            __syncwarp();

            const u64* pp = (const u64*)buf;
            u64 a0 = 0, a1 = 0, a2 = 0, a3 = 0;
            u64 c0 = 0, c1 = 0, c2 = 0, c3 = 0;
            #pragma unroll
            for (int m = 0; m < KDIM / 2; m += 4) {
                u64 q0 = pp[m], q1 = pp[m + 1], q2 = pp[m + 2], q3 = pp[m + 3];
                a0 = ffma2(ep0[m],     q0, a0);  c0 = ffma2(ep1[m],     q0, c0);
                a1 = ffma2(ep0[m + 1], q1, a1);  c1 = ffma2(ep1[m + 1], q1, c1);
                a2 = ffma2(ep0[m + 2], q2, a2);  c2 = ffma2(ep1[m + 2], q2, c2);
                a3 = ffma2(ep0[m + 3], q3, a3);  c3 = ffma2(ep1[m + 3], q3, c3);
            }
            u64 sa = add2(add2(a0, a1), add2(a2, a3));
            u64 sc = add2(add2(c0, c1), add2(c2, c3));
            float sal, sah, scl, sch;
            unpack2(sa, sal, sah); unpack2(sc, scl, sch);
            u64 s = mul2(pack2(sal + sah, scl + sch), U);

            if ((t & RENORM_MASK) == 0) {
                // exact pow2 renorm keyed on lane 0 / state 0
                unsigned bits = (unsigned)s;           // low half = state-0 float bits
                bits = __shfl_sync(0xffffffffu, bits, 0);
                int ex = (int)((bits >> 23) & 0xffu);
                float scale = __uint_as_float((unsigned)(254 - ex) << 23);
                C2 += ex - 127;
                s = mul2(s, pack2(scale, scale));
            }
            p = s;
        }

        // epilogue: third = ln(sum_j P_j) with scale restored
        float p0, p1; unpack2(p, p0, p1);
        float tot = p0 + p1;
        float usum = us;
        #pragma unroll
        for (int off = 16; off; off >>= 1) {
            tot  += __shfl_xor_sync(0xffffffffu, tot, off);
            usum += __shfl_xor_sync(0xffffffffu, usum, off);
        }
        if (lane == 0) {
            float third = (lg2(tot) + (float)C2 + 6.f * (float)(L - 1)) * LN2;
            g_partials[b] = usum - third;
        }
    }

    // -------- deterministic final reduction by the last-arriving block ------
    __threadfence();
    __syncthreads();
    if (threadIdx.x == 0)
        is_last = (atomicAdd(&g_done, 1) == gridDim.x - 1) ? 1 : 0;
    __syncthreads();

    if (is_last) {
        if (threadIdx.x == 0) g_done = 0;   // reset for next graph replay
        __threadfence();
        float s = 0.f;
        for (int i = threadIdx.x; i < BATCH; i += NTHREADS)
            s += g_partials[i];
        red[threadIdx.x] = s;
        __syncthreads();
        #pragma unroll
        for (int off = NTHREADS / 2; off; off >>= 1) {
            if (threadIdx.x < off) red[threadIdx.x] += red[threadIdx.x + off];
            __syncthreads();
        }
        if (threadIdx.x == 0)
            out[0] = -red[0] / (float)BATCH;
    }
}

extern "C" void kernel_launch(void* const* d_in, const int* in_sizes, int n_in,
                              void* d_out, int out_size)
{
    const float* logits  = (const float*)d_in[0];
    const float* trans   = (const float*)d_in[1];
    const int*   gold    = (const int*)d_in[2];
    const int*   seq_len = (const int*)d_in[3];
    float* out = (float*)d_out;

    order_kernel<<<1, 512>>>(seq_len, trans);
    crf_fwd_kernel<<<NBLK, NTHREADS>>>(logits, trans, gold, seq_len, out);
}